// round 16
// baseline (speedup 1.0000x reference)
#include <cuda_runtime.h>
#include <cuda_fp16.h>
#include <cstdint>

// Problem constants
#define BB 8
#define CC 64
#define OO 64
#define HH 80
#define WW 800
#define TW 32            // w per CTA
#define HROWS 8          // h-rows per CTA; M = 8*32 = 256
#define THREADS 256
#define NPAIR 32         // all 64 channels resident as 32 half2 pairs (single K pass)

// Strip: per channel-pair, 14 rows x 40 cols of half2 words
#define S_COLS 40
#define S_ROWS 14
#define PSTRIDE 584      // words per pair (560 + pad); 584 mod 32 == 8 -> A bank = 8*lc + bs (proven)

// Weight stage: half2 [o=64][pair=32] stride 36 words -> B banks (4*lr+lc) all distinct
#define WSTRIDE 36
#define WS_BYTES (OO*WSTRIDE*4)             // 9216

// SMEM layout (byte offsets)
#define OFF_TABLE 0                          // int[9*256] = 9216
#define OFF_WS    9216                       // two weight buffers = 18432
#define OFF_STRIP 27648                      // u32[32*584] = 74752
#define SMEM_TOTAL (OFF_STRIP + NPAIR*PSTRIDE*4)   // 102,400 B -> 2 CTAs/SM

#define EPI_STRIDE 132   // epilogue [o][m-chunk of 128]; 33,792 <= 74,752

// ---------------- helpers ----------------
static __device__ __forceinline__ void mma_f16(float* c,
                                               uint32_t a0, uint32_t a1, uint32_t a2, uint32_t a3,
                                               uint32_t b0, uint32_t b1) {
    asm volatile(
        "mma.sync.aligned.m16n8k16.row.col.f32.f16.f16.f32 "
        "{%0,%1,%2,%3}, {%4,%5,%6,%7}, {%8,%9}, {%0,%1,%2,%3};"
        : "+f"(c[0]), "+f"(c[1]), "+f"(c[2]), "+f"(c[3])
        : "r"(a0), "r"(a1), "r"(a2), "r"(a3), "r"(b0), "r"(b1));
}
static __device__ __forceinline__ uint32_t pack_h2(float lo, float hi) {
    __half2 h = __floats2half2_rn(lo, hi);
    return *(uint32_t*)&h;
}

// ---------------- kernel ----------------
__global__ __launch_bounds__(THREADS, 2)
void AdaptiveConv2d_hmma_kernel(const float* __restrict__ x,
                                const float* __restrict__ dh,
                                const float* __restrict__ dw,
                                const float* __restrict__ weight,
                                const float* __restrict__ bias,
                                float* __restrict__ out)
{
    extern __shared__ __align__(16) char smc[];
    int*      s_table = (int*)(smc + OFF_TABLE);
    uint32_t* strip   = (uint32_t*)(smc + OFF_STRIP);

    const int tid  = threadIdx.x;
    const int lane = tid & 31;
    const int wid  = tid >> 5;
    const int lr   = lane >> 2;     // 0..7
    const int lc   = lane & 3;      // 0..3
    const int mw   = wid & 3;       // m-warp block: rows mw*64..+63 (2 h-rows)
    const int nw   = wid >> 2;      // n-warp block: cols nw*32..+31

    const int b  = blockIdx.z;
    const int h0 = blockIdx.y * HROWS;
    const int w0 = blockIdx.x * TW;

    // ---- index table: base strip position per (tap, m), m = hsel*32 + wl ----
    {
        const int m = tid;                 // 0..255
        const int hsel = m >> 5, wl = m & 31;
        const int h = h0 + hsel;
        const int w = w0 + wl;             // 800 % 32 == 0: always in range
        int dilh = (int)dh[b * WW + w]; if (dilh < 1) dilh = 1;
        int dilw = (int)dw[b * WW + w]; if (dilw < 1) dilw = 1;

        int rows[3], cols[3];
        int d = h - dilh; rows[0] = (d < 0) ? -d : d;              // |h-dil| < H
        rows[1] = h;
        int up = h + dilh; rows[2] = (up < HH) ? up : h;
        int l = w - dilw; cols[0] = (l < 0) ? -l : l;              // |w-dil| < W
        cols[1] = w;
        int rt = w + dilw; cols[2] = (rt < WW) ? rt : (2 * WW - 1 - rt);

#pragma unroll
        for (int ri = 0; ri < 3; ++ri)
#pragma unroll
            for (int ci = 0; ci < 3; ++ci)
                s_table[(ri * 3 + ci) * 256 + m] =
                    (rows[ri] - (h0 - 3)) * S_COLS + (cols[ci] - (w0 - 4));
    }

    // ---- strip load (once): all 32 pairs, 14x40 window, packed half2 ----
    {
        for (int idx = tid; idx < NPAIR * S_ROWS * 10; idx += THREADS) {
            int p   = idx / (S_ROWS * 10);
            int rem = idx - p * (S_ROWS * 10);
            int r   = rem / 10;
            int j4  = rem - r * 10;
            int gr = h0 - 3 + r; gr = (gr < 0) ? 0 : ((gr > HH - 1) ? HH - 1 : gr);
            int gc = w0 - 4 + j4 * 4; gc = (gc < 0) ? 0 : ((gc > WW - 4) ? WW - 4 : gc);
            const float* xp = x + ((size_t)b * CC + 2 * p) * HH * WW + (size_t)gr * WW + gc;
            const float4 v0 = *(const float4*)xp;
            const float4 v1 = *(const float4*)(xp + (size_t)HH * WW);
            uint4 g;
            g.x = pack_h2(v0.x, v1.x);
            g.y = pack_h2(v0.y, v1.y);
            g.z = pack_h2(v0.z, v1.z);
            g.w = pack_h2(v0.w, v1.w);
            *(uint4*)&strip[p * PSTRIDE + r * S_COLS + j4 * 4] = g;
        }
    }

    // weight staging: thread handles o = tid>>2, pairs wpr..wpr+7 (channels 16(tid&3)..+15)
    const int wo  = tid >> 2;            // 0..63
    const int wpr = (tid & 3) * 8;       // 0,8,16,24

    auto stage_weights_reg = [&](const float4 f0, const float4 f1,
                                 const float4 f2, const float4 f3, int buf) {
        uint32_t* wsb = (uint32_t*)(smc + OFF_WS + buf * WS_BYTES) + wo * WSTRIDE + wpr;
        uint4 g0, g1;
        g0.x = pack_h2(f0.x, f0.y); g0.y = pack_h2(f0.z, f0.w);
        g0.z = pack_h2(f1.x, f1.y); g0.w = pack_h2(f1.z, f1.w);
        g1.x = pack_h2(f2.x, f2.y); g1.y = pack_h2(f2.z, f2.w);
        g1.z = pack_h2(f3.x, f3.y); g1.w = pack_h2(f3.z, f3.w);
        *(uint4*)wsb = g0;
        *(uint4*)(wsb + 4) = g1;
    };

    // ---- stage tap-0 weights into buffer 0 ----
    {
        const float* wg = weight + (size_t)wo * CC + 2 * wpr;
        stage_weights_reg(*(const float4*)(wg), *(const float4*)(wg + 4),
                          *(const float4*)(wg + 8), *(const float4*)(wg + 12), 0);
    }
    __syncthreads();

    // ---- accumulators: [mt 0..3][nt 0..3][4] ----
    float acc[4][4][4];
#pragma unroll
    for (int mt = 0; mt < 4; ++mt)
#pragma unroll
        for (int nt = 0; nt < 4; ++nt)
#pragma unroll
            for (int j = 0; j < 4; ++j) acc[mt][nt][j] = 0.0f;

    // ---- 9 tap stages, full K=64 each ----
    for (int t = 0; t < 9; ++t) {
        // prefetch next tap's weights to registers
        float4 wf0, wf1, wf2, wf3;
        if (t + 1 < 9) {
            const float* wg = weight + (size_t)(t + 1) * OO * CC + (size_t)wo * CC + 2 * wpr;
            wf0 = *(const float4*)(wg);
            wf1 = *(const float4*)(wg + 4);
            wf2 = *(const float4*)(wg + 8);
            wf3 = *(const float4*)(wg + 12);
        }

        // per-thread A row bases: rows mw*64 + mt*16 + lr (+8)
        int bs0[4], bs1[4];
#pragma unroll
        for (int mt = 0; mt < 4; ++mt) {
            const int m0 = mw * 64 + mt * 16 + lr;
            bs0[mt] = s_table[t * 256 + m0];
            bs1[mt] = s_table[t * 256 + m0 + 8];
        }

        const uint32_t* sB = (const uint32_t*)(smc + OFF_WS + (t & 1) * WS_BYTES)
                             + (nw * 32 + lr) * WSTRIDE + lc;

        // four k16 groups (ki = 16-channel chunk)
#pragma unroll
        for (int ki = 0; ki < 4; ++ki) {
            uint32_t b0[4], b1[4];
#pragma unroll
            for (int nt = 0; nt < 4; ++nt) {
                b0[nt] = sB[nt * (8 * WSTRIDE) + 8 * ki];
                b1[nt] = sB[nt * (8 * WSTRIDE) + 8 * ki + 4];
            }
            const uint32_t* pA0 = strip + (8 * ki + lc) * PSTRIDE;
            const uint32_t* pA1 = pA0 + 4 * PSTRIDE;
#pragma unroll
            for (int mt = 0; mt < 4; ++mt) {
                const uint32_t a0 = pA0[bs0[mt]];
                const uint32_t a1 = pA0[bs1[mt]];
                const uint32_t a2 = pA1[bs0[mt]];
                const uint32_t a3 = pA1[bs1[mt]];
#pragma unroll
                for (int nt = 0; nt < 4; ++nt)
                    mma_f16(acc[mt][nt], a0, a1, a2, a3, b0[nt], b1[nt]);
            }
        }

        // store prefetched weights into the other buffer
        if (t + 1 < 9) {
            stage_weights_reg(wf0, wf1, wf2, wf3, (t + 1) & 1);
        }
        __syncthreads();
    }

    // ---- epilogue: two 128-row chunks through smem [o][m'] (strip area) ----
    float* epi = (float*)(smc + OFF_STRIP);
    for (int ch = 0; ch < 2; ++ch) {
        __syncthreads();
        if ((mw >> 1) == ch) {          // warps owning m in [ch*128, ch*128+128)
#pragma unroll
            for (int mt = 0; mt < 4; ++mt) {
#pragma unroll
                for (int nt = 0; nt < 4; ++nt) {
                    const int m0 = (mw & 1) * 64 + mt * 16 + lr;
                    const int o0 = nw * 32 + nt * 8 + 2 * lc;
                    epi[(o0    ) * EPI_STRIDE + m0    ] = acc[mt][nt][0];
                    epi[(o0 + 1) * EPI_STRIDE + m0    ] = acc[mt][nt][1];
                    epi[(o0    ) * EPI_STRIDE + m0 + 8] = acc[mt][nt][2];
                    epi[(o0 + 1) * EPI_STRIDE + m0 + 8] = acc[mt][nt][3];
                }
            }
        }
        __syncthreads();
        for (int idx = tid; idx < OO * 128; idx += THREADS) {
            const int o = idx >> 7, mm = idx & 127;
            const int gm = ch * 128 + mm;
            const int w = w0 + (gm & 31);
            const int h = h0 + (gm >> 5);
            out[(((size_t)b * OO + o) * HH + h) * WW + w] =
                epi[o * EPI_STRIDE + mm] + __ldg(&bias[o]);
        }
    }
}

extern "C" void kernel_launch(void* const* d_in, const int* in_sizes, int n_in,
                              void* d_out, int out_size)
{
    const float* x      = (const float*)d_in[0];
    const float* dh     = (const float*)d_in[1];
    const float* dw     = (const float*)d_in[2];
    const float* weight = (const float*)d_in[3];
    const float* bias   = (const float*)d_in[4];
    float* out = (float*)d_out;

    cudaFuncSetAttribute(AdaptiveConv2d_hmma_kernel,
                         cudaFuncAttributeMaxDynamicSharedMemorySize, SMEM_TOTAL);

    dim3 grid(WW / TW, HH / HROWS, BB);   // 25 x 10 x 8 = 2000
    AdaptiveConv2d_hmma_kernel<<<grid, THREADS, SMEM_TOTAL>>>(x, dh, dw, weight, bias, out);
}

// round 17
// speedup vs baseline: 1.0194x; 1.0194x over previous
#include <cuda_runtime.h>
#include <cuda_fp16.h>
#include <cstdint>

// Problem constants
#define BB 8
#define CC 64
#define OO 64
#define HH 80
#define WW 800
#define TW 64            // w per CTA
#define HROWS 4          // h-rows per CTA; M = 4*64 = 256
#define THREADS 256
#define CHALF 32         // channels per K-split pass (2 passes)
#define NHALF 2
#define NPAIR 16         // half2 channel-pairs resident per pass

// Strip: per channel-PAIR, 10 rows x 72 cols of half2 words
#define S_COLS 72
#define S_ROWS 10
#define PSTRIDE 744      // words per pair (720 + pad); 744 mod 32 == 8 -> A bank = 8*lc + bs (proven)

// Weight wall: half2 [tap=9][o=64][pair=16] stride 20 words -> B banks (20*lr+lc) all distinct
#define WST 20
#define WALL_WORDS (9*OO*WST)               // 11520 u32 = 46080 B

// SMEM layout (byte offsets)
#define OFF_TABLE 0                          // int[9*256] = 9216
#define OFF_WALL  9216                       // 46080
#define OFF_STRIP 55296                      // u32[16*744] = 47616
#define SMEM_TOTAL (OFF_STRIP + NPAIR*PSTRIDE*4)   // 102,912 B -> 2 CTAs/SM

#define EPI_STRIDE 132   // epilogue [o][m-chunk of 128]; 33,792 <= 47,616 (strip area)

// ---------------- helpers ----------------
static __device__ __forceinline__ void mma_f16(float* c,
                                               uint32_t a0, uint32_t a1, uint32_t a2, uint32_t a3,
                                               uint32_t b0, uint32_t b1) {
    asm volatile(
        "mma.sync.aligned.m16n8k16.row.col.f32.f16.f16.f32 "
        "{%0,%1,%2,%3}, {%4,%5,%6,%7}, {%8,%9}, {%0,%1,%2,%3};"
        : "+f"(c[0]), "+f"(c[1]), "+f"(c[2]), "+f"(c[3])
        : "r"(a0), "r"(a1), "r"(a2), "r"(a3), "r"(b0), "r"(b1));
}
static __device__ __forceinline__ uint32_t pack_h2(float lo, float hi) {
    __half2 h = __floats2half2_rn(lo, hi);   // .x = even-k channel, .y = odd-k channel
    return *(uint32_t*)&h;
}

// ---------------- kernel ----------------
__global__ __launch_bounds__(THREADS, 2)
void AdaptiveConv2d_hmma_kernel(const float* __restrict__ x,
                                const float* __restrict__ dh,
                                const float* __restrict__ dw,
                                const float* __restrict__ weight,
                                const float* __restrict__ bias,
                                float* __restrict__ out)
{
    extern __shared__ __align__(16) char smc[];
    int*      s_table = (int*)(smc + OFF_TABLE);
    uint32_t* wall    = (uint32_t*)(smc + OFF_WALL);
    uint32_t* strip   = (uint32_t*)(smc + OFF_STRIP);

    const int tid  = threadIdx.x;
    const int lane = tid & 31;
    const int wid  = tid >> 5;
    const int lr   = lane >> 2;     // 0..7
    const int lc   = lane & 3;      // 0..3
    const int mw   = wid & 3;       // m-warp block: rows mw*64..+63
    const int nw   = wid >> 2;      // n-warp block: cols nw*32..+31

    const int b  = blockIdx.z;
    const int h0 = blockIdx.y * HROWS;
    const int w0 = blockIdx.x * TW;

    // ---- index table: base strip position per (tap, m), m = hsel*64 + wl ----
    {
        const int m = tid;                 // 0..255
        const int hsel = m >> 6, wl = m & 63;
        const int h = h0 + hsel;
        int w = w0 + wl; if (w > WW - 1) w = WW - 1;
        int dilh = (int)dh[b * WW + w]; if (dilh < 1) dilh = 1;
        int dilw = (int)dw[b * WW + w]; if (dilw < 1) dilw = 1;

        int rows[3], cols[3];
        int d = h - dilh; rows[0] = (d < 0) ? -d : d;              // |h-dil| < H
        rows[1] = h;
        int up = h + dilh; rows[2] = (up < HH) ? up : h;
        int l = w - dilw; cols[0] = (l < 0) ? -l : l;              // |w-dil| < W
        cols[1] = w;
        int rt = w + dilw; cols[2] = (rt < WW) ? rt : (2 * WW - 1 - rt);

#pragma unroll
        for (int ri = 0; ri < 3; ++ri)
#pragma unroll
            for (int ci = 0; ci < 3; ++ci)
                s_table[(ri * 3 + ci) * 256 + m] =
                    (rows[ri] - (h0 - 3)) * S_COLS + (cols[ci] - (w0 - 4));
    }

    // ---- strip loader: 16 channel-pairs of one half, packed half2 ----
    const float* xb = x + (size_t)b * CC * HH * WW;
    auto load_strip = [&](int half) {
        const float* xh = xb + (size_t)half * CHALF * HH * WW;
        for (int idx = tid; idx < NPAIR * S_ROWS * 18; idx += THREADS) {
            int p   = idx / (S_ROWS * 18);
            int rem = idx - p * (S_ROWS * 18);
            int r   = rem / 18;
            int j4  = rem - r * 18;
            int gr = h0 - 3 + r; gr = (gr < 0) ? 0 : ((gr > HH - 1) ? HH - 1 : gr);
            int gc = w0 - 4 + j4 * 4; gc = (gc < 0) ? 0 : ((gc > WW - 4) ? WW - 4 : gc);
            const size_t off = (size_t)(2 * p) * HH * WW + (size_t)gr * WW + gc;
            const float4 v0 = *(const float4*)&xh[off];
            const float4 v1 = *(const float4*)&xh[off + (size_t)HH * WW];
            uint4 g;
            g.x = pack_h2(v0.x, v1.x);
            g.y = pack_h2(v0.y, v1.y);
            g.z = pack_h2(v0.z, v1.z);
            g.w = pack_h2(v0.w, v1.w);
            *(uint4*)&strip[p * PSTRIDE + r * S_COLS + j4 * 4] = g;
        }
    };

    // ---- weight wall loader: all 9 taps of one half (2304 uint4 stores) ----
    auto load_wall = [&](int half) {
        for (int i = tid; i < 9 * 256; i += THREADS) {
            const int t  = i >> 8;
            const int r  = i & 255;
            const int o  = r >> 2;
            const int p4 = (r & 3) * 4;         // pairs p4..p4+3 = channels 2p4..2p4+7
            const float* wg = weight + ((size_t)t * OO + o) * CC + half * CHALF + 2 * p4;
            const float4 f0 = *(const float4*)(wg);
            const float4 f1 = *(const float4*)(wg + 4);
            uint4 g;
            g.x = pack_h2(f0.x, f0.y);
            g.y = pack_h2(f0.z, f0.w);
            g.z = pack_h2(f1.x, f1.y);
            g.w = pack_h2(f1.z, f1.w);
            *(uint4*)&wall[(t * OO + o) * WST + p4] = g;
        }
    };

    // ---- accumulators: [mt 0..3][nt 0..3][4] ----
    float acc[4][4][4];
#pragma unroll
    for (int mt = 0; mt < 4; ++mt)
#pragma unroll
        for (int nt = 0; nt < 4; ++nt)
#pragma unroll
            for (int j = 0; j < 4; ++j) acc[mt][nt][j] = 0.0f;

    // ---- 2 halves x 9 taps; NO barriers inside the 9-tap mainloop ----
    for (int half = 0; half < NHALF; ++half) {
        if (half) __syncthreads();      // all readers of previous half done
        load_wall(half);
        load_strip(half);
        __syncthreads();                // staging visible

#pragma unroll 1
        for (int t = 0; t < 9; ++t) {
            // per-thread A row bases: rows mw*64 + mt*16 + lr (+8)
            int bs0[4], bs1[4];
#pragma unroll
            for (int mt = 0; mt < 4; ++mt) {
                const int m0 = mw * 64 + mt * 16 + lr;
                bs0[mt] = s_table[t * 256 + m0];
                bs1[mt] = s_table[t * 256 + m0 + 8];
            }

            const uint32_t* sB = wall + (t * OO + nw * 32 + lr) * WST + lc;

            // two k16 groups per tap (ki = 16-channel chunk)
#pragma unroll
            for (int ki = 0; ki < 2; ++ki) {
                uint32_t b0[4], b1[4];
#pragma unroll
                for (int nt = 0; nt < 4; ++nt) {
                    b0[nt] = sB[nt * (8 * WST) + 8 * ki];
                    b1[nt] = sB[nt * (8 * WST) + 8 * ki + 4];
                }
                const uint32_t* pA0 = strip + (8 * ki + lc) * PSTRIDE;
                const uint32_t* pA1 = pA0 + 4 * PSTRIDE;
#pragma unroll
                for (int mt = 0; mt < 4; ++mt) {
                    const uint32_t a0 = pA0[bs0[mt]];
                    const uint32_t a1 = pA0[bs1[mt]];
                    const uint32_t a2 = pA1[bs0[mt]];
                    const uint32_t a3 = pA1[bs1[mt]];
#pragma unroll
                    for (int nt = 0; nt < 4; ++nt)
                        mma_f16(acc[mt][nt], a0, a1, a2, a3, b0[nt], b1[nt]);
                }
            }
        }
    }

    // ---- epilogue: two 128-row chunks through smem [o][m'] (strip area) ----
    float* epi = (float*)(smc + OFF_STRIP);
    for (int ch = 0; ch < 2; ++ch) {
        __syncthreads();
        if ((mw >> 1) == ch) {          // warps owning m in [ch*128, ch*128+128)
#pragma unroll
            for (int mt = 0; mt < 4; ++mt) {
#pragma unroll
                for (int nt = 0; nt < 4; ++nt) {
                    const int m0 = (mw & 1) * 64 + mt * 16 + lr;
                    const int o0 = nw * 32 + nt * 8 + 2 * lc;
                    epi[(o0    ) * EPI_STRIDE + m0    ] = acc[mt][nt][0];
                    epi[(o0 + 1) * EPI_STRIDE + m0    ] = acc[mt][nt][1];
                    epi[(o0    ) * EPI_STRIDE + m0 + 8] = acc[mt][nt][2];
                    epi[(o0 + 1) * EPI_STRIDE + m0 + 8] = acc[mt][nt][3];
                }
            }
        }
        __syncthreads();
        for (int idx = tid; idx < OO * 128; idx += THREADS) {
            const int o = idx >> 7, mm = idx & 127;
            const int gm = ch * 128 + mm;
            const int w = w0 + (gm & 63);
            const int h = h0 + (gm >> 6);
            if (w < WW)
                out[(((size_t)b * OO + o) * HH + h) * WW + w] =
                    epi[o * EPI_STRIDE + mm] + __ldg(&bias[o]);
        }
    }
}

extern "C" void kernel_launch(void* const* d_in, const int* in_sizes, int n_in,
                              void* d_out, int out_size)
{
    const float* x      = (const float*)d_in[0];
    const float* dh     = (const float*)d_in[1];
    const float* dw     = (const float*)d_in[2];
    const float* weight = (const float*)d_in[3];
    const float* bias   = (const float*)d_in[4];
    float* out = (float*)d_out;

    cudaFuncSetAttribute(AdaptiveConv2d_hmma_kernel,
                         cudaFuncAttributeMaxDynamicSharedMemorySize, SMEM_TOTAL);

    dim3 grid((WW + TW - 1) / TW, HH / HROWS, BB);   // 13 x 20 x 8 = 2080
    AdaptiveConv2d_hmma_kernel<<<grid, THREADS, SMEM_TOTAL>>>(x, dh, dw, weight, bias, out);
}